// round 4
// baseline (speedup 1.0000x reference)
#include <cuda_runtime.h>
#include <math.h>

#define DM 512
#define NH 8
#define HD 64
#define NB 4
#define SQ 2048
#define M_ROWS (NB*SQ)   // 8192
#define BH (NB*NH)       // 32

// Scratch (no allocation allowed): q,k,v,ctx in [B,H,S,Dh] layout
__device__ float g_q[(size_t)BH*SQ*HD];
__device__ float g_k[(size_t)BH*SQ*HD];
__device__ float g_v[(size_t)BH*SQ*HD];
__device__ float g_ctx[(size_t)BH*SQ*HD];

// ---------------------------------------------------------------------------
// Projection GEMM: out = X[M,512] @ W^T[512,512] + b, scattered to [B,H,S,Dh]
// which: 0->g_q, 1->g_k, 2->g_v
// 64x64 tile, TK=16, 256 threads, 4x4 per-thread micro-tile
// ---------------------------------------------------------------------------
__global__ void proj_kernel(const float* __restrict__ X, const float* __restrict__ W,
                            const float* __restrict__ bias, int which)
{
    __shared__ float As[16][65];
    __shared__ float Bs[16][65];
    const int tid = threadIdx.x;
    const int tx = tid & 15, ty = tid >> 4;
    const int m0 = blockIdx.y * 64, n0 = blockIdx.x * 64;
    float* __restrict__ out = (which == 0) ? g_q : (which == 1) ? g_k : g_v;

    float acc[4][4] = {};
    for (int k0 = 0; k0 < DM; k0 += 16) {
        #pragma unroll
        for (int r = 0; r < 4; r++) {
            int idx = tid + r * 256;
            int mm = idx >> 4, kk = idx & 15;
            As[kk][mm] = X[(size_t)(m0 + mm) * DM + k0 + kk];
            Bs[kk][mm] = W[(size_t)(n0 + mm) * DM + k0 + kk];
        }
        __syncthreads();
        #pragma unroll
        for (int kk = 0; kk < 16; kk++) {
            float a[4], b[4];
            #pragma unroll
            for (int i = 0; i < 4; i++) a[i] = As[kk][ty * 4 + i];
            #pragma unroll
            for (int j = 0; j < 4; j++) b[j] = Bs[kk][tx * 4 + j];
            #pragma unroll
            for (int i = 0; i < 4; i++)
                #pragma unroll
                for (int j = 0; j < 4; j++)
                    acc[i][j] += a[i] * b[j];
        }
        __syncthreads();
    }
    #pragma unroll
    for (int i = 0; i < 4; i++) {
        int m = m0 + ty * 4 + i;
        int b_ = m / SQ, s = m % SQ;
        #pragma unroll
        for (int j = 0; j < 4; j++) {
            int n = n0 + tx * 4 + j;
            int h = n >> 6, dh = n & 63;
            out[(size_t)((b_ * NH + h) * SQ + s) * HD + dh] = acc[i][j] + bias[n];
        }
    }
}

// ---------------------------------------------------------------------------
// Causal QK^T: scores[bh,i,j] = q.k/8 for j<=i, else 0; writes straight into
// the attention output region. Fully-masked tiles write zeros and skip compute.
// ---------------------------------------------------------------------------
__global__ void qk_kernel(float* __restrict__ attn)
{
    const int bh = blockIdx.z;
    const int m0 = blockIdx.y * 64, n0 = blockIdx.x * 64;
    float* __restrict__ out = attn + (size_t)bh * SQ * SQ;
    const int tid = threadIdx.x;

    if (n0 > m0 + 63) {  // tile entirely above diagonal
        #pragma unroll
        for (int r = 0; r < 16; r++) {
            int idx = tid + r * 256;
            int i = idx >> 6, j = idx & 63;
            out[(size_t)(m0 + i) * SQ + n0 + j] = 0.f;
        }
        return;
    }

    const float* __restrict__ q = g_q + (size_t)bh * SQ * HD;
    const float* __restrict__ k = g_k + (size_t)bh * SQ * HD;
    __shared__ float As[16][65];
    __shared__ float Bs[16][65];
    const int tx = tid & 15, ty = tid >> 4;
    float acc[4][4] = {};

    for (int k0 = 0; k0 < HD; k0 += 16) {
        #pragma unroll
        for (int r = 0; r < 4; r++) {
            int idx = tid + r * 256;
            int mm = idx >> 4, kk = idx & 15;
            As[kk][mm] = q[(size_t)(m0 + mm) * HD + k0 + kk];
            Bs[kk][mm] = k[(size_t)(n0 + mm) * HD + k0 + kk];
        }
        __syncthreads();
        #pragma unroll
        for (int kk = 0; kk < 16; kk++) {
            float a[4], b[4];
            #pragma unroll
            for (int i = 0; i < 4; i++) a[i] = As[kk][ty * 4 + i];
            #pragma unroll
            for (int j = 0; j < 4; j++) b[j] = Bs[kk][tx * 4 + j];
            #pragma unroll
            for (int i = 0; i < 4; i++)
                #pragma unroll
                for (int j = 0; j < 4; j++)
                    acc[i][j] += a[i] * b[j];
        }
        __syncthreads();
    }
    #pragma unroll
    for (int i = 0; i < 4; i++) {
        int gi = m0 + ty * 4 + i;
        #pragma unroll
        for (int j = 0; j < 4; j++) {
            int gj = n0 + tx * 4 + j;
            out[(size_t)gi * SQ + gj] = (gj <= gi) ? acc[i][j] * 0.125f : 0.f;
        }
    }
}

// ---------------------------------------------------------------------------
// In-place row softmax over the causal prefix (cols 0..i). One block per row.
// ---------------------------------------------------------------------------
__global__ void softmax_kernel(float* __restrict__ attn)
{
    const int row = blockIdx.x;         // bh*SQ + i
    const int i = row & (SQ - 1);
    float* __restrict__ p = attn + (size_t)row * SQ;
    const int n = i + 1;
    const int tid = threadIdx.x;
    __shared__ float red[128];

    float mx = -1e30f;
    for (int j = tid; j < n; j += 128) mx = fmaxf(mx, p[j]);
    red[tid] = mx; __syncthreads();
    #pragma unroll
    for (int s = 64; s > 0; s >>= 1) {
        if (tid < s) red[tid] = fmaxf(red[tid], red[tid + s]);
        __syncthreads();
    }
    mx = red[0]; __syncthreads();

    float sum = 0.f;
    for (int j = tid; j < n; j += 128) {
        float e = __expf(p[j] - mx);
        p[j] = e;
        sum += e;
    }
    red[tid] = sum; __syncthreads();
    #pragma unroll
    for (int s = 64; s > 0; s >>= 1) {
        if (tid < s) red[tid] += red[tid + s];
        __syncthreads();
    }
    float inv = 1.f / red[0];
    for (int j = tid; j < n; j += 128) p[j] *= inv;
}

// ---------------------------------------------------------------------------
// AV GEMM: ctx[bh, i, :] = sum_{j<=i} attn[bh,i,j] * v[bh,j,:]
// K-loop truncated at the block's diagonal (upper triangle is zero anyway).
// ---------------------------------------------------------------------------
__global__ void av_kernel(const float* __restrict__ attn)
{
    const int bh = blockIdx.z;
    const int m0 = blockIdx.y * 64;
    const float* __restrict__ A = attn + (size_t)bh * SQ * SQ;
    const float* __restrict__ Vh = g_v + (size_t)bh * SQ * HD;
    float* __restrict__ C = g_ctx + (size_t)bh * SQ * HD;
    __shared__ float As[16][65];
    __shared__ float Bs[16][65];
    const int tid = threadIdx.x;
    const int tx = tid & 15, ty = tid >> 4;
    float acc[4][4] = {};

    const int kend = m0 + 64;  // causal truncation
    for (int k0 = 0; k0 < kend; k0 += 16) {
        #pragma unroll
        for (int r = 0; r < 4; r++) {
            int idx = tid + r * 256;
            int mm = idx >> 4, kk = idx & 15;
            As[kk][mm] = A[(size_t)(m0 + mm) * SQ + k0 + kk];
            int nn = idx & 63, kk2 = idx >> 6;
            Bs[kk2][nn] = Vh[(size_t)(k0 + kk2) * HD + nn];
        }
        __syncthreads();
        #pragma unroll
        for (int kk = 0; kk < 16; kk++) {
            float a[4], b[4];
            #pragma unroll
            for (int i = 0; i < 4; i++) a[i] = As[kk][ty * 4 + i];
            #pragma unroll
            for (int j = 0; j < 4; j++) b[j] = Bs[kk][tx * 4 + j];
            #pragma unroll
            for (int i = 0; i < 4; i++)
                #pragma unroll
                for (int j = 0; j < 4; j++)
                    acc[i][j] += a[i] * b[j];
        }
        __syncthreads();
    }
    #pragma unroll
    for (int i = 0; i < 4; i++)
        #pragma unroll
        for (int j = 0; j < 4; j++)
            C[(size_t)(m0 + ty * 4 + i) * HD + tx * 4 + j] = acc[i][j];
}

// ---------------------------------------------------------------------------
// Output projection: x = ctx(reshaped [8192,512]) @ w_o^T + b_o
// A is gathered from [B,H,S,Dh] layout.
// ---------------------------------------------------------------------------
__global__ void outproj_kernel(const float* __restrict__ W, const float* __restrict__ bias,
                               float* __restrict__ out)
{
    __shared__ float As[16][65];
    __shared__ float Bs[16][65];
    const int tid = threadIdx.x;
    const int tx = tid & 15, ty = tid >> 4;
    const int m0 = blockIdx.y * 64, n0 = blockIdx.x * 64;
    float acc[4][4] = {};

    for (int k0 = 0; k0 < DM; k0 += 16) {
        #pragma unroll
        for (int r = 0; r < 4; r++) {
            int idx = tid + r * 256;
            int mm = idx >> 4, kk = idx & 15;
            int m = m0 + mm, k = k0 + kk;
            int b_ = m / SQ, s = m % SQ;
            int h = k >> 6, dh = k & 63;
            As[kk][mm] = g_ctx[(size_t)((b_ * NH + h) * SQ + s) * HD + dh];
            Bs[kk][mm] = W[(size_t)(n0 + mm) * DM + k0 + kk];
        }
        __syncthreads();
        #pragma unroll
        for (int kk = 0; kk < 16; kk++) {
            float a[4], b[4];
            #pragma unroll
            for (int i = 0; i < 4; i++) a[i] = As[kk][ty * 4 + i];
            #pragma unroll
            for (int j = 0; j < 4; j++) b[j] = Bs[kk][tx * 4 + j];
            #pragma unroll
            for (int i = 0; i < 4; i++)
                #pragma unroll
                for (int j = 0; j < 4; j++)
                    acc[i][j] += a[i] * b[j];
        }
        __syncthreads();
    }
    #pragma unroll
    for (int i = 0; i < 4; i++) {
        int m = m0 + ty * 4 + i;
        #pragma unroll
        for (int j = 0; j < 4; j++) {
            int n = n0 + tx * 4 + j;
            out[(size_t)m * DM + n] = acc[i][j] + bias[n];
        }
    }
}

// ---------------------------------------------------------------------------
extern "C" void kernel_launch(void* const* d_in, const int* in_sizes, int n_in,
                              void* d_out, int out_size)
{
    const float* Q   = (const float*)d_in[0];
    const float* K   = (const float*)d_in[1];
    const float* V   = (const float*)d_in[2];
    // d_in[3] is the causal mask — computed analytically instead.
    const float* w_q = (const float*)d_in[4];
    const float* b_q = (const float*)d_in[5];
    const float* w_k = (const float*)d_in[6];
    const float* b_k = (const float*)d_in[7];
    const float* w_v = (const float*)d_in[8];
    const float* b_v = (const float*)d_in[9];
    const float* w_o = (const float*)d_in[10];
    const float* b_o = (const float*)d_in[11];

    float* out_x = (float*)d_out;
    float* attn  = (float*)d_out + (size_t)M_ROWS * DM;

    dim3 blk(256);
    dim3 gproj(DM / 64, M_ROWS / 64);           // 8 x 128

    proj_kernel<<<gproj, blk>>>(Q, w_q, b_q, 0);
    proj_kernel<<<gproj, blk>>>(K, w_k, b_k, 1);
    proj_kernel<<<gproj, blk>>>(V, w_v, b_v, 2);

    qk_kernel<<<dim3(SQ / 64, SQ / 64, BH), blk>>>(attn);      // 32x32x32
    softmax_kernel<<<BH * SQ, 128>>>(attn);                    // 65536 rows
    av_kernel<<<dim3(1, SQ / 64, BH), blk>>>(attn);            // 1x32x32
    outproj_kernel<<<dim3(DM / 64, M_ROWS / 64), blk>>>(w_o, b_o, out_x);
}

// round 5
// speedup vs baseline: 1.4061x; 1.4061x over previous
#include <cuda_runtime.h>
#include <math.h>
#include <stdint.h>

#define DM 512
#define NH 8
#define HD 64
#define NB 4
#define SQ 2048
#define M_ROWS (NB*SQ)   // 8192
#define BH (NB*NH)       // 32

// Scratch (no allocation allowed): q,k,v,ctx in [B,H,S,Dh] layout
__device__ float g_q[(size_t)BH*SQ*HD];
__device__ float g_k[(size_t)BH*SQ*HD];
__device__ float g_v[(size_t)BH*SQ*HD];
__device__ float g_ctx[(size_t)BH*SQ*HD];

// ---------------------------------------------------------------------------
// tf32x3 helpers: split fp32 into tf32 hi + tf32 lo; 3 MMAs give ~fp32 accuracy
// ---------------------------------------------------------------------------
__device__ __forceinline__ uint32_t f2tf32(float f){
    uint32_t r;
    asm("cvt.rna.tf32.f32 %0, %1;" : "=r"(r) : "f"(f));
    return r;
}
__device__ __forceinline__ void split_tf32(float f, uint32_t& h, uint32_t& l){
    uint32_t hb = f2tf32(f);
    h = hb;
    l = f2tf32(f - __uint_as_float(hb));   // exact residual, re-quantized
}
__device__ __forceinline__ void mma8(float* c, const uint32_t* a, const uint32_t* b){
    asm volatile("mma.sync.aligned.m16n8k8.row.col.f32.tf32.tf32.f32 "
        "{%0,%1,%2,%3}, {%4,%5,%6,%7}, {%8,%9}, {%0,%1,%2,%3};\n"
        : "+f"(c[0]), "+f"(c[1]), "+f"(c[2]), "+f"(c[3])
        : "r"(a[0]), "r"(a[1]), "r"(a[2]), "r"(a[3]), "r"(b[0]), "r"(b[1]));
}

// ---------------------------------------------------------------------------
// Shared 128x64x16 chunk compute: 8 warps as 4(M)x2(N), warp tile 32x32.
// As is k-major [16][136] (m up to 128), Bs is k-major [16][72] (n up to 64).
// Padding chosen so fragment loads hit 32 distinct banks (8*tg + g pattern).
// ---------------------------------------------------------------------------
__device__ __forceinline__ void mma_chunk(const float As[16][136], const float Bs[16][72],
                                          float acc[2][4][4], int wm, int wn, int g, int tg)
{
    #pragma unroll
    for (int s = 0; s < 2; s++){
        const int kb = 8*s;
        uint32_t Ah[2][4], Al[2][4], Bh[4][2], Bl[4][2];
        #pragma unroll
        for (int am = 0; am < 2; am++){
            const int mb = wm*32 + am*16 + g;
            split_tf32(As[kb+tg  ][mb  ], Ah[am][0], Al[am][0]);
            split_tf32(As[kb+tg  ][mb+8], Ah[am][1], Al[am][1]);
            split_tf32(As[kb+tg+4][mb  ], Ah[am][2], Al[am][2]);
            split_tf32(As[kb+tg+4][mb+8], Ah[am][3], Al[am][3]);
        }
        #pragma unroll
        for (int bn = 0; bn < 4; bn++){
            const int nb = wn*32 + bn*8 + g;
            split_tf32(Bs[kb+tg  ][nb], Bh[bn][0], Bl[bn][0]);
            split_tf32(Bs[kb+tg+4][nb], Bh[bn][1], Bl[bn][1]);
        }
        #pragma unroll
        for (int am = 0; am < 2; am++)
            #pragma unroll
            for (int bn = 0; bn < 4; bn++){
                mma8(acc[am][bn], Ah[am], Bh[bn]);   // hi*hi
                mma8(acc[am][bn], Ah[am], Bl[bn]);   // hi*lo
                mma8(acc[am][bn], Al[am], Bh[bn]);   // lo*hi
            }
    }
}

// ---------------------------------------------------------------------------
// Projection: out = X[8192,512] @ W^T + b, scattered to [B,H,S,Dh]
// ---------------------------------------------------------------------------
__global__ void proj_kernel(const float* __restrict__ X, const float* __restrict__ W,
                            const float* __restrict__ bias, int which)
{
    __shared__ __align__(16) float As[16][136];
    __shared__ __align__(16) float Bs[16][72];
    const int tid = threadIdx.x;
    const int lane = tid & 31, warp = tid >> 5;
    const int wm = warp & 3, wn = warp >> 2;
    const int g = lane >> 2, tg = lane & 3;
    const int m0 = blockIdx.y * 128, n0 = blockIdx.x * 64;
    float* __restrict__ out = (which == 0) ? g_q : (which == 1) ? g_k : g_v;

    float acc[2][4][4] = {};
    for (int k0 = 0; k0 < DM; k0 += 16){
        #pragma unroll
        for (int i = 0; i < 2; i++){
            int idx = tid + 256*i;
            int mm = idx & 127, q4 = idx >> 7;
            float4 v = *(const float4*)&X[(size_t)(m0+mm)*DM + k0 + q4*4];
            As[q4*4+0][mm]=v.x; As[q4*4+1][mm]=v.y; As[q4*4+2][mm]=v.z; As[q4*4+3][mm]=v.w;
        }
        {
            int nn = tid & 63, q4 = tid >> 6;
            float4 v = *(const float4*)&W[(size_t)(n0+nn)*DM + k0 + q4*4];
            Bs[q4*4+0][nn]=v.x; Bs[q4*4+1][nn]=v.y; Bs[q4*4+2][nn]=v.z; Bs[q4*4+3][nn]=v.w;
        }
        __syncthreads();
        mma_chunk(As, Bs, acc, wm, wn, g, tg);
        __syncthreads();
    }
    #pragma unroll
    for (int am = 0; am < 2; am++)
      #pragma unroll
      for (int bn = 0; bn < 4; bn++)
        #pragma unroll
        for (int c = 0; c < 4; c++){
            int m = m0 + wm*32 + am*16 + g + ((c>>1)<<3);
            int n = n0 + wn*32 + bn*8 + tg*2 + (c&1);
            int b_ = m >> 11, s = m & (SQ-1);
            int h = n >> 6, dh = n & 63;
            out[(size_t)((b_*NH + h)*SQ + s)*HD + dh] = acc[am][bn][c] + bias[n];
        }
}

// ---------------------------------------------------------------------------
// Causal QK^T: 128x64 tiles; upper tiles zero-filled; diagonal band masked.
// ---------------------------------------------------------------------------
__global__ void qk_kernel(float* __restrict__ attn)
{
    const int bh = blockIdx.z;
    const int m0 = blockIdx.y * 128, n0 = blockIdx.x * 64;
    float* __restrict__ out = attn + (size_t)bh * SQ * SQ;
    const int tid = threadIdx.x;

    if (n0 >= m0 + 128){   // tile entirely above diagonal
        #pragma unroll
        for (int i = 0; i < 8; i++){
            int idx = tid + 256*i;            // 2048 float4s
            int r = idx >> 4, cq = idx & 15;
            *(float4*)&out[(size_t)(m0+r)*SQ + n0 + cq*4] = make_float4(0.f,0.f,0.f,0.f);
        }
        return;
    }

    const float* __restrict__ q = g_q + (size_t)bh * SQ * HD;
    const float* __restrict__ k = g_k + (size_t)bh * SQ * HD;
    __shared__ __align__(16) float As[16][136];
    __shared__ __align__(16) float Bs[16][72];
    const int lane = tid & 31, warp = tid >> 5;
    const int wm = warp & 3, wn = warp >> 2;
    const int g = lane >> 2, tg = lane & 3;
    float acc[2][4][4] = {};

    for (int k0 = 0; k0 < HD; k0 += 16){
        #pragma unroll
        for (int i = 0; i < 2; i++){
            int idx = tid + 256*i;
            int mm = idx & 127, q4 = idx >> 7;
            float4 v = *(const float4*)&q[(size_t)(m0+mm)*HD + k0 + q4*4];
            As[q4*4+0][mm]=v.x; As[q4*4+1][mm]=v.y; As[q4*4+2][mm]=v.z; As[q4*4+3][mm]=v.w;
        }
        {
            int nn = tid & 63, q4 = tid >> 6;
            float4 v = *(const float4*)&k[(size_t)(n0+nn)*HD + k0 + q4*4];
            Bs[q4*4+0][nn]=v.x; Bs[q4*4+1][nn]=v.y; Bs[q4*4+2][nn]=v.z; Bs[q4*4+3][nn]=v.w;
        }
        __syncthreads();
        mma_chunk(As, Bs, acc, wm, wn, g, tg);
        __syncthreads();
    }
    #pragma unroll
    for (int am = 0; am < 2; am++)
      #pragma unroll
      for (int bn = 0; bn < 4; bn++)
        #pragma unroll
        for (int c = 0; c < 4; c++){
            int gi = m0 + wm*32 + am*16 + g + ((c>>1)<<3);
            int gj = n0 + wn*32 + bn*8 + tg*2 + (c&1);
            out[(size_t)gi*SQ + gj] = (gj <= gi) ? acc[am][bn][c]*0.125f : 0.f;
        }
}

// ---------------------------------------------------------------------------
// Row softmax: whole row held in registers (256 thr x 8 vals) — 1 read, 1 write.
// ---------------------------------------------------------------------------
__global__ void softmax_kernel(float* __restrict__ attn)
{
    const int row = blockIdx.x;          // bh*SQ + i
    const int i = row & (SQ - 1);
    float* __restrict__ p = attn + (size_t)row * SQ;
    const int n = i + 1;
    const int tid = threadIdx.x;
    __shared__ float red[256];

    float v[8];
    float mx = -1e30f;
    #pragma unroll
    for (int t = 0; t < 8; t++){
        int j = tid + 256*t;
        if (j < n){ v[t] = p[j]; mx = fmaxf(mx, v[t]); }
    }
    red[tid] = mx; __syncthreads();
    #pragma unroll
    for (int s = 128; s > 0; s >>= 1){
        if (tid < s) red[tid] = fmaxf(red[tid], red[tid+s]);
        __syncthreads();
    }
    mx = red[0]; __syncthreads();

    float sum = 0.f;
    #pragma unroll
    for (int t = 0; t < 8; t++){
        int j = tid + 256*t;
        if (j < n){ v[t] = __expf(v[t] - mx); sum += v[t]; }
    }
    red[tid] = sum; __syncthreads();
    #pragma unroll
    for (int s = 128; s > 0; s >>= 1){
        if (tid < s) red[tid] += red[tid+s];
        __syncthreads();
    }
    float inv = 1.f / red[0];
    #pragma unroll
    for (int t = 0; t < 8; t++){
        int j = tid + 256*t;
        if (j < n) p[j] = v[t] * inv;    // cols > i stay exactly 0 (written by qk)
    }
}

// ---------------------------------------------------------------------------
// AV: ctx[128-row tile] = P[128, 0..m0+128] @ V; K truncated at diagonal.
// ---------------------------------------------------------------------------
__global__ void av_kernel(const float* __restrict__ attn)
{
    const int bh = blockIdx.z;
    const int m0 = blockIdx.y * 128;
    const float* __restrict__ A  = attn + (size_t)bh*SQ*SQ;
    const float* __restrict__ Vh = g_v  + (size_t)bh*SQ*HD;
    float* __restrict__ C = g_ctx + (size_t)bh*SQ*HD;
    __shared__ __align__(16) float As[16][136];
    __shared__ __align__(16) float Bs[16][72];
    const int tid = threadIdx.x;
    const int lane = tid & 31, warp = tid >> 5;
    const int wm = warp & 3, wn = warp >> 2;
    const int g = lane >> 2, tg = lane & 3;
    float acc[2][4][4] = {};

    const int kend = m0 + 128;          // causal truncation (P is 0 above diag)
    for (int k0 = 0; k0 < kend; k0 += 16){
        #pragma unroll
        for (int i = 0; i < 2; i++){
            int idx = tid + 256*i;
            int mm = idx & 127, q4 = idx >> 7;
            float4 v = *(const float4*)&A[(size_t)(m0+mm)*SQ + k0 + q4*4];
            As[q4*4+0][mm]=v.x; As[q4*4+1][mm]=v.y; As[q4*4+2][mm]=v.z; As[q4*4+3][mm]=v.w;
        }
        {
            int kk = tid >> 4, nq = tid & 15;     // V transpose: Bs[n-major per k row]
            float4 v = *(const float4*)&Vh[(size_t)(k0+kk)*HD + nq*4];
            *(float4*)&Bs[kk][nq*4] = v;
        }
        __syncthreads();
        mma_chunk(As, Bs, acc, wm, wn, g, tg);
        __syncthreads();
    }
    #pragma unroll
    for (int am = 0; am < 2; am++)
      #pragma unroll
      for (int bn = 0; bn < 4; bn++)
        #pragma unroll
        for (int c = 0; c < 4; c++){
            int m = m0 + wm*32 + am*16 + g + ((c>>1)<<3);
            int ncol = wn*32 + bn*8 + tg*2 + (c&1);
            C[(size_t)m*HD + ncol] = acc[am][bn][c];
        }
}

// ---------------------------------------------------------------------------
// Output projection: x = ctx([B,H,S,Dh] gathered as [8192,512]) @ w_o^T + b_o
// ---------------------------------------------------------------------------
__global__ void outproj_kernel(const float* __restrict__ W, const float* __restrict__ bias,
                               float* __restrict__ outp)
{
    __shared__ __align__(16) float As[16][136];
    __shared__ __align__(16) float Bs[16][72];
    const int tid = threadIdx.x;
    const int lane = tid & 31, warp = tid >> 5;
    const int wm = warp & 3, wn = warp >> 2;
    const int g = lane >> 2, tg = lane & 3;
    const int m0 = blockIdx.y * 128, n0 = blockIdx.x * 64;
    float acc[2][4][4] = {};

    for (int k0 = 0; k0 < DM; k0 += 16){
        #pragma unroll
        for (int i = 0; i < 2; i++){
            int idx = tid + 256*i;
            int mm = idx & 127, q4 = idx >> 7;
            int m = m0 + mm;
            int b_ = m >> 11, s = m & (SQ-1);
            int kk = k0 + q4*4;
            int h = kk >> 6, dh = kk & 63;      // float4 stays inside one head
            float4 v = *(const float4*)&g_ctx[(size_t)((b_*NH + h)*SQ + s)*HD + dh];
            As[q4*4+0][mm]=v.x; As[q4*4+1][mm]=v.y; As[q4*4+2][mm]=v.z; As[q4*4+3][mm]=v.w;
        }
        {
            int nn = tid & 63, q4 = tid >> 6;
            float4 v = *(const float4*)&W[(size_t)(n0+nn)*DM + k0 + q4*4];
            Bs[q4*4+0][nn]=v.x; Bs[q4*4+1][nn]=v.y; Bs[q4*4+2][nn]=v.z; Bs[q4*4+3][nn]=v.w;
        }
        __syncthreads();
        mma_chunk(As, Bs, acc, wm, wn, g, tg);
        __syncthreads();
    }
    #pragma unroll
    for (int am = 0; am < 2; am++)
      #pragma unroll
      for (int bn = 0; bn < 4; bn++)
        #pragma unroll
        for (int c = 0; c < 4; c++){
            int m = m0 + wm*32 + am*16 + g + ((c>>1)<<3);
            int n = n0 + wn*32 + bn*8 + tg*2 + (c&1);
            outp[(size_t)m*DM + n] = acc[am][bn][c] + bias[n];
        }
}

// ---------------------------------------------------------------------------
extern "C" void kernel_launch(void* const* d_in, const int* in_sizes, int n_in,
                              void* d_out, int out_size)
{
    const float* Q   = (const float*)d_in[0];
    const float* K   = (const float*)d_in[1];
    const float* V   = (const float*)d_in[2];
    // d_in[3] is the causal mask — computed analytically instead.
    const float* w_q = (const float*)d_in[4];
    const float* b_q = (const float*)d_in[5];
    const float* w_k = (const float*)d_in[6];
    const float* b_k = (const float*)d_in[7];
    const float* w_v = (const float*)d_in[8];
    const float* b_v = (const float*)d_in[9];
    const float* w_o = (const float*)d_in[10];
    const float* b_o = (const float*)d_in[11];

    float* out_x = (float*)d_out;
    float* attn  = (float*)d_out + (size_t)M_ROWS * DM;

    dim3 blk(256);
    proj_kernel<<<dim3(DM/64, M_ROWS/128), blk>>>(Q, w_q, b_q, 0);
    proj_kernel<<<dim3(DM/64, M_ROWS/128), blk>>>(K, w_k, b_k, 1);
    proj_kernel<<<dim3(DM/64, M_ROWS/128), blk>>>(V, w_v, b_v, 2);

    qk_kernel<<<dim3(SQ/64, SQ/128, BH), blk>>>(attn);
    softmax_kernel<<<BH*SQ, 256>>>(attn);
    av_kernel<<<dim3(1, SQ/128, BH), blk>>>(attn);
    outproj_kernel<<<dim3(DM/64, M_ROWS/128), blk>>>(w_o, b_o, out_x);
}